// round 1
// baseline (speedup 1.0000x reference)
#include <cuda_runtime.h>

#define SEQ   2048
#define BATCH 4096
#define IN    4
#define HID   3
#define UNR   8

__global__ void __launch_bounds__(32, 1)
rnn_relu_kernel(const float* __restrict__ x,      // [SEQ, BATCH, 4]
                const float* __restrict__ h0,     // [1, BATCH, 3]
                const float* __restrict__ W_ih,   // [3, 4]
                const float* __restrict__ W_hh,   // [3, 3]
                const float* __restrict__ b_ih,   // [3]
                const float* __restrict__ b_hh,   // [3]
                float* __restrict__ out)          // [SEQ*BATCH*3 + BATCH*3]
{
    const int b = blockIdx.x * blockDim.x + threadIdx.x;
    if (b >= BATCH) return;

    // Hoist weights/biases to registers (uniform across threads).
    float wih[HID][IN];
    float whh[HID][HID];
    float bias[HID];
#pragma unroll
    for (int j = 0; j < HID; j++) {
#pragma unroll
        for (int i = 0; i < IN; i++) wih[j][i] = W_ih[j * IN + i];
#pragma unroll
        for (int i = 0; i < HID; i++) whh[j][i] = W_hh[j * HID + i];
        bias[j] = b_ih[j] + b_hh[j];
    }

    float h0r = h0[b * HID + 0];
    float h1r = h0[b * HID + 1];
    float h2r = h0[b * HID + 2];

    const float4* __restrict__ xv = (const float4*)x;  // [SEQ][BATCH] of float4
    float* __restrict__ outs = out;
    float* __restrict__ hlast = out + (size_t)SEQ * BATCH * HID;

    // Prime the pipeline: preload first UNR timesteps of x for this batch lane.
    float4 buf[UNR];
#pragma unroll
    for (int k = 0; k < UNR; k++)
        buf[k] = xv[(size_t)k * BATCH + b];

    for (int t0 = 0; t0 < SEQ; t0 += UNR) {
        // Prefetch next group (independent of recurrence -> deep MLP).
        float4 nbuf[UNR];
        if (t0 + UNR < SEQ) {
#pragma unroll
            for (int k = 0; k < UNR; k++)
                nbuf[k] = xv[(size_t)(t0 + UNR + k) * BATCH + b];
        }

#pragma unroll
        for (int k = 0; k < UNR; k++) {
            const float4 xt = buf[k];

            // Input projection (independent of h -> off the serial chain).
            float p0 = fmaf(wih[0][0], xt.x, bias[0]);
            p0 = fmaf(wih[0][1], xt.y, p0);
            p0 = fmaf(wih[0][2], xt.z, p0);
            p0 = fmaf(wih[0][3], xt.w, p0);
            float p1 = fmaf(wih[1][0], xt.x, bias[1]);
            p1 = fmaf(wih[1][1], xt.y, p1);
            p1 = fmaf(wih[1][2], xt.z, p1);
            p1 = fmaf(wih[1][3], xt.w, p1);
            float p2 = fmaf(wih[2][0], xt.x, bias[2]);
            p2 = fmaf(wih[2][1], xt.y, p2);
            p2 = fmaf(wih[2][2], xt.z, p2);
            p2 = fmaf(wih[2][3], xt.w, p2);

            // Recurrent part (serial dependence on previous h).
            float a0 = fmaf(whh[0][0], h0r, p0);
            a0 = fmaf(whh[0][1], h1r, a0);
            a0 = fmaf(whh[0][2], h2r, a0);
            float a1 = fmaf(whh[1][0], h0r, p1);
            a1 = fmaf(whh[1][1], h1r, a1);
            a1 = fmaf(whh[1][2], h2r, a1);
            float a2 = fmaf(whh[2][0], h0r, p2);
            a2 = fmaf(whh[2][1], h1r, a2);
            a2 = fmaf(whh[2][2], h2r, a2);

            h0r = fmaxf(a0, 0.0f);
            h1r = fmaxf(a1, 0.0f);
            h2r = fmaxf(a2, 0.0f);

            const size_t o = ((size_t)(t0 + k) * BATCH + b) * HID;
            outs[o + 0] = h0r;
            outs[o + 1] = h1r;
            outs[o + 2] = h2r;
        }

#pragma unroll
        for (int k = 0; k < UNR; k++)
            buf[k] = nbuf[k];
    }

    hlast[b * HID + 0] = h0r;
    hlast[b * HID + 1] = h1r;
    hlast[b * HID + 2] = h2r;
}

extern "C" void kernel_launch(void* const* d_in, const int* in_sizes, int n_in,
                              void* d_out, int out_size)
{
    const float* x    = (const float*)d_in[0];
    const float* h0   = (const float*)d_in[1];
    const float* W_ih = (const float*)d_in[2];
    const float* W_hh = (const float*)d_in[3];
    const float* b_ih = (const float*)d_in[4];
    const float* b_hh = (const float*)d_in[5];
    float* out = (float*)d_out;

    // 4096 chains, one per thread; 32-thread blocks so each warp owns an SMSP
    // and blocks spread across SMs.
    rnn_relu_kernel<<<BATCH / 32, 32>>>(x, h0, W_ih, W_hh, b_ih, b_hh, out);
}

// round 2
// speedup vs baseline: 2.0163x; 2.0163x over previous
#include <cuda_runtime.h>
#include <cstdint>

#define SEQ    2048
#define BATCH  4096
#define IN     4
#define HID    3
#define UNR    8                  // timesteps per pipeline stage
#define STAGES 4                  // smem pipeline depth
#define NGRP   (SEQ / UNR)        // 256 groups

__device__ __forceinline__ void cp_async16(void* smem_dst, const void* gmem_src) {
    uint32_t s;
    asm("{ .reg .u64 t; cvta.to.shared.u64 t, %1; cvt.u32.u64 %0, t; }"
        : "=r"(s) : "l"(smem_dst));
    asm volatile("cp.async.ca.shared.global [%0], [%1], 16;"
                 :: "r"(s), "l"(gmem_src) : "memory");
}
__device__ __forceinline__ void cp_async_commit() {
    asm volatile("cp.async.commit_group;" ::: "memory");
}
template <int N>
__device__ __forceinline__ void cp_async_wait() {
    asm volatile("cp.async.wait_group %0;" :: "n"(N) : "memory");
}

__global__ void __launch_bounds__(32, 1)
rnn_relu_kernel(const float* __restrict__ x,      // [SEQ, BATCH, 4]
                const float* __restrict__ h0,     // [1, BATCH, 3]
                const float* __restrict__ W_ih,   // [3, 4]
                const float* __restrict__ W_hh,   // [3, 3]
                const float* __restrict__ b_ih,   // [3]
                const float* __restrict__ b_hh,   // [3]
                float* __restrict__ out)
{
    // One warp per block; each thread owns one batch chain and its own smem lane.
    __shared__ float4 xs[STAGES][UNR][32];

    const int lane = threadIdx.x;
    const int b = blockIdx.x * 32 + lane;

    // Uniform weights/biases in registers.
    float wih[HID][IN];
    float whh[HID][HID];
    float bias[HID];
#pragma unroll
    for (int j = 0; j < HID; j++) {
#pragma unroll
        for (int i = 0; i < IN; i++) wih[j][i] = W_ih[j * IN + i];
#pragma unroll
        for (int i = 0; i < HID; i++) whh[j][i] = W_hh[j * HID + i];
        bias[j] = b_ih[j] + b_hh[j];
    }

    float h0r = h0[b * HID + 0];
    float h1r = h0[b * HID + 1];
    float h2r = h0[b * HID + 2];

    const float4* __restrict__ xv = (const float4*)x;  // [SEQ][BATCH]
    float* __restrict__ outs = out;
    float* __restrict__ hlast = out + (size_t)SEQ * BATCH * HID;

    // Prime STAGES-1 = 3 stages (24 timesteps of lookahead).
#pragma unroll
    for (int s = 0; s < STAGES - 1; s++) {
#pragma unroll
        for (int k = 0; k < UNR; k++)
            cp_async16(&xs[s][k][lane], &xv[(size_t)(s * UNR + k) * BATCH + b]);
        cp_async_commit();
    }

    for (int g = 0; g < NGRP; g++) {
        const int stage = g & (STAGES - 1);

        // Oldest outstanding group (this stage) must be complete.
        cp_async_wait<STAGES - 2>();
        // No sync needed: each thread reads only the smem it wrote itself,
        // and cp.async completion is per-thread via wait_group.

        const int t0 = g * UNR;
#pragma unroll
        for (int k = 0; k < UNR; k++) {
            const float4 xt = xs[stage][k][lane];

            // Input projection — independent of the recurrence chain.
            float p0 = fmaf(wih[0][0], xt.x, bias[0]);
            p0 = fmaf(wih[0][1], xt.y, p0);
            p0 = fmaf(wih[0][2], xt.z, p0);
            p0 = fmaf(wih[0][3], xt.w, p0);
            float p1 = fmaf(wih[1][0], xt.x, bias[1]);
            p1 = fmaf(wih[1][1], xt.y, p1);
            p1 = fmaf(wih[1][2], xt.z, p1);
            p1 = fmaf(wih[1][3], xt.w, p1);
            float p2 = fmaf(wih[2][0], xt.x, bias[2]);
            p2 = fmaf(wih[2][1], xt.y, p2);
            p2 = fmaf(wih[2][2], xt.z, p2);
            p2 = fmaf(wih[2][3], xt.w, p2);

            // Recurrent update (serial chain, ~16 cyc — hidden under issue).
            float a0 = fmaf(whh[0][0], h0r, p0);
            a0 = fmaf(whh[0][1], h1r, a0);
            a0 = fmaf(whh[0][2], h2r, a0);
            float a1 = fmaf(whh[1][0], h0r, p1);
            a1 = fmaf(whh[1][1], h1r, a1);
            a1 = fmaf(whh[1][2], h2r, a1);
            float a2 = fmaf(whh[2][0], h0r, p2);
            a2 = fmaf(whh[2][1], h1r, a2);
            a2 = fmaf(whh[2][2], h2r, a2);

            h0r = fmaxf(a0, 0.0f);
            h1r = fmaxf(a1, 0.0f);
            h2r = fmaxf(a2, 0.0f);

            const size_t o = ((size_t)(t0 + k) * BATCH + b) * HID;
            outs[o + 0] = h0r;
            outs[o + 1] = h1r;
            outs[o + 2] = h2r;
        }

        // Refill this group's stage slot for group g + STAGES - 1.
        const int gnext = g + STAGES - 1;
        if (gnext < NGRP) {
            const int ns = gnext & (STAGES - 1);
#pragma unroll
            for (int k = 0; k < UNR; k++)
                cp_async16(&xs[ns][k][lane],
                           &xv[(size_t)(gnext * UNR + k) * BATCH + b]);
        }
        cp_async_commit();  // keep group accounting uniform even on tail
    }

    hlast[b * HID + 0] = h0r;
    hlast[b * HID + 1] = h1r;
    hlast[b * HID + 2] = h2r;
}

extern "C" void kernel_launch(void* const* d_in, const int* in_sizes, int n_in,
                              void* d_out, int out_size)
{
    const float* x    = (const float*)d_in[0];
    const float* h0   = (const float*)d_in[1];
    const float* W_ih = (const float*)d_in[2];
    const float* W_hh = (const float*)d_in[3];
    const float* b_ih = (const float*)d_in[4];
    const float* b_hh = (const float*)d_in[5];
    float* out = (float*)d_out;

    rnn_relu_kernel<<<BATCH / 32, 32>>>(x, h0, W_ih, W_hh, b_ih, b_hh, out);
}